// round 6
// baseline (speedup 1.0000x reference)
#include <cuda_runtime.h>

// ---------------------------------------------------------------------------
// MeanPooling: out[b,:] = mean of x[i,:] over rows i with batch[i]==b
// x: (N,128) fp32, batch: (N,) sorted int64-or-int32, out: (4096,128) fp32
// R5: ONE persistent kernel. Grid 888 with launch_bounds(256,6) => whole grid
// co-resident (6/SM x 148 SMs; also fits GB300's 152). Software grid barrier
// (arrive counter) then fused divide epilogue -- removes the 5us k_div node.
// Scratch g_sums/g_counts and barrier counters are re-zeroed before kernel
// exit so every graph replay starts from clean state (BSS starts zero).
// ---------------------------------------------------------------------------

#define D 128
#define MAXB 8192
#define MAXOUT (MAXB * D)
#define GRID 888
#define TPB 256

__device__ float g_sums[MAXOUT];  // accumulation scratch
__device__ int g_counts[MAXB];    // per-segment row counts
__device__ int g_arrive;          // grid-barrier arrive counter
__device__ int g_depart;          // grid-barrier depart counter

// Detect dtype of batch buffer. Reads only within the first n 32-bit words
// (in-bounds for both layouts). int64 LE: odd words are high halves == 0
// (values < 4096). int32 sorted data: tail words ~ num_graphs-1 (nonzero).
__device__ __forceinline__ int detect_is64(const unsigned int* __restrict__ w,
                                           int n) {
    int top = n - 1;
    if ((top & 1) == 0) top--;          // largest odd index <= n-1
    int nz = 0;
#pragma unroll 1
    for (int k = 0; k < 32; k++) {
        int idx = top - 2 * k;
        if (idx < 1) break;
        if (w[idx] != 0u) { nz = 1; break; }
    }
    return (nz == 0) ? 1 : 0;
}

__device__ __forceinline__ void flush_seg(int seg, int lane,
                                          const float4& acc, int cnt) {
    float* p = g_sums + (size_t)seg * D + lane * 4;
    atomicAdd(p + 0, acc.x);
    atomicAdd(p + 1, acc.y);
    atomicAdd(p + 2, acc.z);
    atomicAdd(p + 3, acc.w);
    if (lane == 0) atomicAdd(&g_counts[seg], cnt);
}

__global__ void __launch_bounds__(TPB, 6) k_fused(const float4* __restrict__ x4,
                                                  const void* __restrict__ batch,
                                                  float4* __restrict__ out,
                                                  int n, int n4) {
    const int tid = threadIdx.x;
    const int lane = tid & 31;

    // ---------------- phase 1: segmented accumulation ----------------
    {
        const int wid = (blockIdx.x << 3) + (tid >> 5);
        const int tw = GRID << 3;
        const int per = (n + tw - 1) / tw;
        int r0 = wid * per;
        int r1 = min(r0 + per, n);

        if (r0 < r1) {
            const int is64 = detect_is64((const unsigned int*)batch, n);
            const int* bw = (const int*)batch;
            const int ish = is64 ? 1 : 0;   // int64 LE: low word at bw[2i]

            float4 acc = make_float4(0.f, 0.f, 0.f, 0.f);
            int cur = bw[r0 << ish];
            int cnt = 0;

            int r = r0;
            for (; r + 4 <= r1; r += 4) {
                const float4* p = x4 + (size_t)r * 32 + lane;
                float4 v0 = __ldcs(p);
                float4 v1 = __ldcs(p + 32);
                float4 v2 = __ldcs(p + 64);
                float4 v3 = __ldcs(p + 96);
                int blast = bw[(r + 3) << ish];
                if (blast == cur) {
                    acc.x += v0.x + v1.x + v2.x + v3.x;
                    acc.y += v0.y + v1.y + v2.y + v3.y;
                    acc.z += v0.z + v1.z + v2.z + v3.z;
                    acc.w += v0.w + v1.w + v2.w + v3.w;
                    cnt += 4;
                } else {
                    float4 v[4] = {v0, v1, v2, v3};
#pragma unroll
                    for (int k = 0; k < 4; k++) {
                        int b = bw[(r + k) << ish];
                        if (b != cur) {
                            flush_seg(cur, lane, acc, cnt);
                            acc = make_float4(0.f, 0.f, 0.f, 0.f);
                            cnt = 0;
                            cur = b;
                        }
                        acc.x += v[k].x; acc.y += v[k].y;
                        acc.z += v[k].z; acc.w += v[k].w;
                        cnt++;
                    }
                }
            }
            for (; r < r1; r++) {
                int b = bw[r << ish];
                if (b != cur) {
                    flush_seg(cur, lane, acc, cnt);
                    acc = make_float4(0.f, 0.f, 0.f, 0.f);
                    cnt = 0;
                    cur = b;
                }
                float4 v = __ldcs(x4 + (size_t)r * 32 + lane);
                acc.x += v.x; acc.y += v.y; acc.z += v.z; acc.w += v.w;
                cnt++;
            }
            flush_seg(cur, lane, acc, cnt);
        }
    }

    // ---------------- grid barrier (all GRID blocks co-resident) -----------
    __syncthreads();
    if (tid == 0) {
        __threadfence();                       // publish this block's atomics
        atomicAdd(&g_arrive, 1);
        while (*(volatile int*)&g_arrive != GRID) {
            __nanosleep(64);
        }
    }
    __syncthreads();
    __threadfence();                           // acquire all blocks' sums

    // ---------------- phase 2: fused divide + scratch re-zero --------------
    {
        int i = blockIdx.x * TPB + tid;
        if (i < n4) {
            int seg = i >> 5;                  // (i*4) / 128
            float c = (float)g_counts[seg];
            float rinv = __frcp_rn(fmaxf(c, 1.0f));
            float4* s4 = (float4*)g_sums;
            float4 v = s4[i];
            v.x *= rinv; v.y *= rinv; v.z *= rinv; v.w *= rinv;
            out[i] = v;
            s4[i] = make_float4(0.f, 0.f, 0.f, 0.f);
            if ((i & 31) == 0) g_counts[seg] = 0;
        }
    }

    // ---------------- depart: last block resets barrier counters -----------
    __syncthreads();
    if (tid == 0) {
        __threadfence();
        int t = atomicAdd(&g_depart, 1);
        if (t == GRID - 1) {                   // everyone passed the spin
            g_arrive = 0;
            g_depart = 0;
        }
    }
}

extern "C" void kernel_launch(void* const* d_in, const int* in_sizes, int n_in,
                              void* d_out, int out_size) {
    const float* x = (const float*)d_in[0];
    const void* batch = d_in[1];

    int n = in_sizes[0] / D;               // number of rows
    int n4 = out_size / 4;                 // float4 elements in output

    k_fused<<<GRID, TPB>>>((const float4*)x, batch, (float4*)d_out, n, n4);
}